// round 1
// baseline (speedup 1.0000x reference)
#include <cuda_runtime.h>

#define BATCH 4096
#define N_AG  32
#define N_HE  8
#define F_IN  256
#define F_OUT 128
#define TB    16          // batch elements per block
#define THREADS 256

__global__ __launch_bounds__(THREADS) void hgcn_fused_kernel(
    const float* __restrict__ in,      // [BATCH, N_AG, F_IN]
    const float* __restrict__ lin_w,   // [F_IN, F_OUT]
    const float* __restrict__ hgcn_b,  // [F_OUT]
    const float* __restrict__ out_w,   // [F_OUT, F_OUT]
    const float* __restrict__ out_b,   // [F_OUT]
    float* __restrict__ out)           // [BATCH*N_AG, F_OUT]
{
    __shared__ float sm[TB][F_IN];     // mean features, 16 KB
    __shared__ float sy[TB][F_OUT];    //  8 KB
    __shared__ float sz[TB][F_OUT];    //  8 KB

    const int t  = threadIdx.x;
    const int B0 = blockIdx.x * TB;

    // ---- Stage A: m[b] = mean over 32 agents of input[b,a,:] ----
    // thread t == feature index (F_IN == THREADS); loads are coalesced:
    // a warp reads 32 consecutive floats per (b,a) row.
    for (int b = 0; b < TB; ++b) {
        const float* p = in + ((size_t)(B0 + b) * N_AG) * F_IN + t;
        float s0 = 0.f, s1 = 0.f, s2 = 0.f, s3 = 0.f;
        #pragma unroll
        for (int a = 0; a < N_AG; a += 4) {
            s0 += p[(a + 0) * F_IN];
            s1 += p[(a + 1) * F_IN];
            s2 += p[(a + 2) * F_IN];
            s3 += p[(a + 3) * F_IN];
        }
        sm[b][t] = (s0 + s1 + s2 + s3) * (1.0f / N_AG);
    }
    __syncthreads();

    const int j  = t & (F_OUT - 1);   // output column 0..127
    const int rg = t >> 7;            // row group 0/1
    const int i0 = rg * (TB / 2);     // 8 rows per group

    // ---- Stage B: y = m @ lin_w + hgcn_bias ----
    {
        float acc[TB / 2];
        #pragma unroll
        for (int i = 0; i < TB / 2; ++i) acc[i] = 0.f;
        for (int k = 0; k < F_IN; ++k) {
            float w = lin_w[k * F_OUT + j];        // coalesced, L1/L2-resident
            #pragma unroll
            for (int i = 0; i < TB / 2; ++i)
                acc[i] += sm[i0 + i][k] * w;       // smem broadcast
        }
        float hb = hgcn_b[j];
        #pragma unroll
        for (int i = 0; i < TB / 2; ++i)
            sy[i0 + i][j] = acc[i] + hb;
    }
    __syncthreads();

    // ---- Stage C: z = relu(y @ out_w + out_b) ----
    {
        float acc[TB / 2];
        #pragma unroll
        for (int i = 0; i < TB / 2; ++i) acc[i] = 0.f;
        for (int k = 0; k < F_OUT; ++k) {
            float w = out_w[k * F_OUT + j];
            #pragma unroll
            for (int i = 0; i < TB / 2; ++i)
                acc[i] += sy[i0 + i][k] * w;
        }
        float ob = out_b[j];
        #pragma unroll
        for (int i = 0; i < TB / 2; ++i) {
            float v = acc[i] + ob;
            sz[i0 + i][j] = v > 0.f ? v : 0.f;
        }
    }
    __syncthreads();

    // ---- Stage D: broadcast each z[b] to 32 agent rows, float4 stores ----
    // This block's output region is contiguous: TB*N_AG*F_OUT floats.
    float4* out4 = (float4*)(out + (size_t)B0 * N_AG * F_OUT);
    const float4* z4 = (const float4*)sz;            // [TB][F_OUT/4]
    const int total4 = TB * N_AG * (F_OUT / 4);      // 16384
    #pragma unroll 4
    for (int o = t; o < total4; o += THREADS) {
        int row = o >> 5;          // / (F_OUT/4) == 32 float4 per row
        int f4  = o & 31;
        int b   = row >> 5;        // / N_AG
        out4[o] = z4[b * 32 + f4];
    }
}

extern "C" void kernel_launch(void* const* d_in, const int* in_sizes, int n_in,
                              void* d_out, int out_size) {
    const float* in     = (const float*)d_in[0];
    const float* lin_w  = (const float*)d_in[1];
    const float* hgcn_b = (const float*)d_in[2];
    const float* out_w  = (const float*)d_in[3];
    const float* out_b  = (const float*)d_in[4];
    // d_in[5] = node_idx, d_in[6] = edge_idx : dense incidence, analytically folded.
    float* out = (float*)d_out;

    dim3 grid(BATCH / TB);
    dim3 block(THREADS);
    hgcn_fused_kernel<<<grid, block>>>(in, lin_w, hgcn_b, out_w, out_b, out);
}

// round 2
// speedup vs baseline: 1.0621x; 1.0621x over previous
#include <cuda_runtime.h>

#define BATCH 4096
#define N_AG  32
#define N_HE  8
#define F_IN  256
#define F_OUT 128
#define TB    8           // batch elements per block  -> grid = 512
#define TBH   (TB / 2)    // rows per compute thread
#define THREADS 256

__global__ __launch_bounds__(THREADS) void hgcn_fused_kernel(
    const float* __restrict__ in,      // [BATCH, N_AG, F_IN]
    const float* __restrict__ lin_w,   // [F_IN, F_OUT]
    const float* __restrict__ hgcn_b,  // [F_OUT]
    const float* __restrict__ out_w,   // [F_OUT, F_OUT]
    const float* __restrict__ out_b,   // [F_OUT]
    float* __restrict__ out)           // [BATCH*N_AG, F_OUT]
{
    __shared__ float sm[TB][F_IN];     // mean features, 8 KB
    __shared__ float sy[TB][F_OUT];    // 4 KB
    __shared__ float sz[TB][F_OUT];    // 4 KB

    const int t  = threadIdx.x;
    const int B0 = blockIdx.x * TB;

    // ---- Stage A: m[b] = mean over 32 agents, float2 loads, full unroll ----
    // thread t -> float2 feature index f2 (0..127), batch half bh (0/1).
    // A warp reads 32 consecutive float2 = 256B per instruction, coalesced.
    // 32 independent loads per (thread, b): deep MLP for DRAM latency hiding.
    {
        const int f2 = t & 127;
        const int bh = t >> 7;
        #pragma unroll
        for (int ob = 0; ob < TB; ob += 2) {
            const int b = ob + bh;
            const float2* p =
                (const float2*)(in + ((size_t)(B0 + b) * N_AG) * F_IN) + f2;
            float2 s0 = {0.f, 0.f}, s1 = {0.f, 0.f};
            float2 s2 = {0.f, 0.f}, s3 = {0.f, 0.f};
            #pragma unroll
            for (int a = 0; a < N_AG; a += 4) {
                float2 v0 = p[(a + 0) * (F_IN / 2)];
                float2 v1 = p[(a + 1) * (F_IN / 2)];
                float2 v2 = p[(a + 2) * (F_IN / 2)];
                float2 v3 = p[(a + 3) * (F_IN / 2)];
                s0.x += v0.x; s0.y += v0.y;
                s1.x += v1.x; s1.y += v1.y;
                s2.x += v2.x; s2.y += v2.y;
                s3.x += v3.x; s3.y += v3.y;
            }
            float2 r;
            r.x = ((s0.x + s1.x) + (s2.x + s3.x)) * (1.0f / N_AG);
            r.y = ((s0.y + s1.y) + (s2.y + s3.y)) * (1.0f / N_AG);
            ((float2*)sm[b])[f2] = r;
        }
    }
    __syncthreads();

    const int j  = t & (F_OUT - 1);   // output column 0..127
    const int rg = t >> 7;            // row group 0/1
    const int i0 = rg * TBH;          // TBH rows per group

    // ---- Stage B: y = m @ lin_w + hgcn_bias ----
    {
        float acc[TBH];
        #pragma unroll
        for (int i = 0; i < TBH; ++i) acc[i] = 0.f;
        for (int k = 0; k < F_IN; ++k) {
            float w = lin_w[k * F_OUT + j];        // coalesced, L1/L2-resident
            #pragma unroll
            for (int i = 0; i < TBH; ++i)
                acc[i] += sm[i0 + i][k] * w;       // smem broadcast within warp
        }
        float hb = hgcn_b[j];
        #pragma unroll
        for (int i = 0; i < TBH; ++i)
            sy[i0 + i][j] = acc[i] + hb;
    }
    __syncthreads();

    // ---- Stage C: z = relu(y @ out_w + out_b) ----
    {
        float acc[TBH];
        #pragma unroll
        for (int i = 0; i < TBH; ++i) acc[i] = 0.f;
        for (int k = 0; k < F_OUT; ++k) {
            float w = out_w[k * F_OUT + j];
            #pragma unroll
            for (int i = 0; i < TBH; ++i)
                acc[i] += sy[i0 + i][k] * w;
        }
        float ob = out_b[j];
        #pragma unroll
        for (int i = 0; i < TBH; ++i) {
            float v = acc[i] + ob;
            sz[i0 + i][j] = v > 0.f ? v : 0.f;
        }
    }
    __syncthreads();

    // ---- Stage D: broadcast each z[b] to 32 agent rows, float4 stores ----
    // This block's output region is contiguous: TB*N_AG*F_OUT floats.
    float4* out4 = (float4*)(out + (size_t)B0 * N_AG * F_OUT);
    const float4* z4 = (const float4*)sz;            // [TB][F_OUT/4]
    const int total4 = TB * N_AG * (F_OUT / 4);      // 8192
    #pragma unroll 8
    for (int o = t; o < total4; o += THREADS) {
        int row = o >> 5;          // 32 float4 per row
        int f4  = o & 31;
        int b   = row >> 5;        // / N_AG
        out4[o] = z4[b * 32 + f4];
    }
}

extern "C" void kernel_launch(void* const* d_in, const int* in_sizes, int n_in,
                              void* d_out, int out_size) {
    const float* in     = (const float*)d_in[0];
    const float* lin_w  = (const float*)d_in[1];
    const float* hgcn_b = (const float*)d_in[2];
    const float* out_w  = (const float*)d_in[3];
    const float* out_b  = (const float*)d_in[4];
    // d_in[5] = node_idx, d_in[6] = edge_idx : dense incidence, analytically folded.
    float* out = (float*)d_out;

    dim3 grid(BATCH / TB);
    dim3 block(THREADS);
    hgcn_fused_kernel<<<grid, block>>>(in, lin_w, hgcn_b, out_w, out_b, out);
}

// round 3
// speedup vs baseline: 1.2217x; 1.1503x over previous
#include <cuda_runtime.h>

#define BATCH 4096
#define N_AG  32
#define F_IN  256
#define F_OUT 128

// Scratch (device-global: no allocation allowed)
__device__ float g_means[BATCH * F_IN];    // 4 MiB
__device__ float g_z[BATCH * F_OUT];       // 2 MiB

// ---------- packed f32x2 helpers (SASS FFMA2 path, PTX-only) ----------
__device__ __forceinline__ unsigned long long pack2(float a, float b) {
    unsigned long long r;
    asm("mov.b64 %0, {%1, %2};" : "=l"(r) : "f"(a), "f"(b));
    return r;
}
__device__ __forceinline__ unsigned long long fma2(unsigned long long a,
                                                   unsigned long long b,
                                                   unsigned long long c) {
    unsigned long long d;
    asm("fma.rn.f32x2 %0, %1, %2, %3;" : "=l"(d) : "l"(a), "l"(b), "l"(c));
    return d;
}
__device__ __forceinline__ float2 unpack2(unsigned long long v) {
    float2 f;
    asm("mov.b64 {%0, %1}, %2;" : "=f"(f.x), "=f"(f.y) : "l"(v));
    return f;
}

// ================= K1: mean over agents =================
// grid 1024 x 256 threads; thread = (float4 column f4, batch-in-block bi)
__global__ __launch_bounds__(256) void k1_mean(const float* __restrict__ in)
{
    const int t  = threadIdx.x;
    const int f4 = t & 63;          // 64 float4 per row
    const int bi = t >> 6;          // 4 batch elements per block
    const int b  = blockIdx.x * 4 + bi;

    const float4* p = (const float4*)(in + (size_t)b * N_AG * F_IN) + f4;
    float4 a0 = {0,0,0,0}, a1 = {0,0,0,0}, a2 = {0,0,0,0}, a3 = {0,0,0,0};
    #pragma unroll
    for (int a = 0; a < N_AG; a += 4) {
        float4 v0 = p[(a + 0) * (F_IN / 4)];
        float4 v1 = p[(a + 1) * (F_IN / 4)];
        float4 v2 = p[(a + 2) * (F_IN / 4)];
        float4 v3 = p[(a + 3) * (F_IN / 4)];
        a0.x += v0.x; a0.y += v0.y; a0.z += v0.z; a0.w += v0.w;
        a1.x += v1.x; a1.y += v1.y; a1.z += v1.z; a1.w += v1.w;
        a2.x += v2.x; a2.y += v2.y; a2.z += v2.z; a2.w += v2.w;
        a3.x += v3.x; a3.y += v3.y; a3.z += v3.z; a3.w += v3.w;
    }
    float4 r;
    r.x = ((a0.x + a1.x) + (a2.x + a3.x)) * (1.0f / N_AG);
    r.y = ((a0.y + a1.y) + (a2.y + a3.y)) * (1.0f / N_AG);
    r.z = ((a0.z + a1.z) + (a2.z + a3.z)) * (1.0f / N_AG);
    r.w = ((a0.w + a1.w) + (a2.w + a3.w)) * (1.0f / N_AG);
    ((float4*)g_means)[(size_t)b * (F_IN / 4) + f4] = r;
}

// ================= K2: z = relu((m@W1+b1)@W2+b2) =================
// grid 256 x 256; TB=16 rows per block. Packed-f32x2 over k-pairs.
#define TB 16
__global__ __launch_bounds__(256) void k2_mlp(
    const float* __restrict__ lin_w,   // [F_IN, F_OUT]
    const float* __restrict__ hgcn_b,  // [F_OUT]
    const float* __restrict__ out_w,   // [F_OUT, F_OUT]
    const float* __restrict__ out_b)   // [F_OUT]
{
    __shared__ float sm[TB][F_IN];     // 16 KB
    __shared__ float sy[TB][F_OUT];    //  8 KB

    const int t  = threadIdx.x;
    const int B0 = blockIdx.x * TB;

    // load mean tile (coalesced; thread = feature)
    #pragma unroll
    for (int r = 0; r < TB; ++r)
        sm[r][t] = g_means[(size_t)(B0 + r) * F_IN + t];
    __syncthreads();

    const int j  = t & (F_OUT - 1);   // column
    const int g  = t >> 7;            // row group (0/1), 8 rows each
    const int r0 = g * 8;

    // ---- stage B: y = m @ lin_w + hgcn_bias ----
    {
        unsigned long long acc[8];
        #pragma unroll
        for (int i = 0; i < 8; ++i) acc[i] = pack2(0.f, 0.f);
        for (int k = 0; k < F_IN; k += 2) {
            float w0 = lin_w[(k + 0) * F_OUT + j];
            float w1 = lin_w[(k + 1) * F_OUT + j];
            unsigned long long wp = pack2(w0, w1);
            #pragma unroll
            for (int i = 0; i < 8; ++i) {
                // LDS.64 of {m[r][k], m[r][k+1]} (8B aligned, warp broadcast)
                unsigned long long mv =
                    *(const unsigned long long*)&sm[r0 + i][k];
                acc[i] = fma2(mv, wp, acc[i]);
            }
        }
        float hb = hgcn_b[j];
        #pragma unroll
        for (int i = 0; i < 8; ++i) {
            float2 p = unpack2(acc[i]);
            sy[r0 + i][j] = p.x + p.y + hb;
        }
    }
    __syncthreads();

    // ---- stage C: z = relu(y @ out_w + out_b) ----
    {
        unsigned long long acc[8];
        #pragma unroll
        for (int i = 0; i < 8; ++i) acc[i] = pack2(0.f, 0.f);
        for (int k = 0; k < F_OUT; k += 2) {
            float w0 = out_w[(k + 0) * F_OUT + j];
            float w1 = out_w[(k + 1) * F_OUT + j];
            unsigned long long wp = pack2(w0, w1);
            #pragma unroll
            for (int i = 0; i < 8; ++i) {
                unsigned long long yv =
                    *(const unsigned long long*)&sy[r0 + i][k];
                acc[i] = fma2(yv, wp, acc[i]);
            }
        }
        float ob = out_b[j];
        #pragma unroll
        for (int i = 0; i < 8; ++i) {
            float2 p = unpack2(acc[i]);
            float v = p.x + p.y + ob;
            g_z[(size_t)(B0 + r0 + i) * F_OUT + j] = v > 0.f ? v : 0.f;
        }
    }
}

// ================= K3: broadcast z to 32 agent rows =================
// grid 2048 x 256; block owns 2 batch elements = 2048 contiguous float4
__global__ __launch_bounds__(256) void k3_bcast(float* __restrict__ out)
{
    const int t  = threadIdx.x;
    const int b0 = blockIdx.x * 2;
    float4* out4 = (float4*)out + (size_t)b0 * N_AG * (F_OUT / 4);
    const float4* z4 = (const float4*)g_z + (size_t)b0 * (F_OUT / 4);

    #pragma unroll 8
    for (int o = t; o < 2 * N_AG * (F_OUT / 4); o += 256) {
        int b  = o >> 10;          // / (N_AG * 32)
        int f4 = o & 31;           // float4 within row
        out4[o] = z4[b * (F_OUT / 4) + f4];   // L1/L2-resident read
    }
}

extern "C" void kernel_launch(void* const* d_in, const int* in_sizes, int n_in,
                              void* d_out, int out_size) {
    const float* in     = (const float*)d_in[0];
    const float* lin_w  = (const float*)d_in[1];
    const float* hgcn_b = (const float*)d_in[2];
    const float* out_w  = (const float*)d_in[3];
    const float* out_b  = (const float*)d_in[4];
    // d_in[5], d_in[6]: dense incidence indices, analytically folded.
    float* out = (float*)d_out;

    k1_mean <<<BATCH / 4, 256>>>(in);
    k2_mlp  <<<BATCH / TB, 256>>>(lin_w, hgcn_b, out_w, out_b);
    k3_bcast<<<BATCH / 2, 256>>>(out);
}